// round 3
// baseline (speedup 1.0000x reference)
#include <cuda_runtime.h>

#define CUTOFF 8.0f
#define MAXK 32
#define MAXE (1 << 20)

// Per-edge precompute: (ux, uy, uz, f(|r|)) where u = r/|r|.
__device__ float4 g_edge[MAXE];
// CSR grouping of e2 by src[e2].
__device__ int g_cnt[MAXE];
__device__ int g_off[MAXE];
__device__ int g_cur[MAXE];
__device__ int g_list[MAXE];
__device__ int g_N;
__device__ int g_degv;
// Fallback-path coefficient storage (generic K only).
__device__ float4 g_fc[MAXK];
__device__ float4 g_gc[MAXK];
__device__ int    g_deg;

// ===========================================================================
// Compile-time-K natural cubic spline (uniform knots). All-register Thomas.
// ===========================================================================
template <int K>
__device__ __forceinline__ void build_spline_reg(const float* __restrict__ y,
                                                 float h, float4* sh_out) {
    float yv[K];
#pragma unroll
    for (int i = 0; i < K; i++) yv[i] = y[i];

    const float inv_h = 1.0f / h;
    float dy[K - 1];
#pragma unroll
    for (int i = 0; i < K - 1; i++) dy[i] = (yv[i + 1] - yv[i]) * inv_h;

    constexpr int n = K - 2;
    float M[K];
    M[0] = 0.0f;
    M[K - 1] = 0.0f;
    if (n > 0) {
        float cp[n], dp[n];
        cp[0] = 0.25f;
        dp[0] = 6.0f * (dy[1] - dy[0]) * inv_h * 0.25f;
#pragma unroll
        for (int i = 1; i < n; i++) {
            float rd = 1.0f / (4.0f - cp[i - 1]);
            cp[i] = rd;
            dp[i] = (6.0f * (dy[i + 1] - dy[i]) * inv_h - dp[i - 1]) * rd;
        }
        M[n] = dp[n - 1];
#pragma unroll
        for (int i = n - 2; i >= 0; i--) M[i + 1] = dp[i] - cp[i] * M[i + 2];
    }

    constexpr float SIXTH = 1.0f / 6.0f;
#pragma unroll
    for (int i = 0; i < K - 1; i++) {
        sh_out[i] = make_float4(yv[i],
                                dy[i] - h * (2.0f * M[i] + M[i + 1]) * SIXTH,
                                0.5f * M[i],
                                (M[i + 1] - M[i]) * inv_h * SIXTH);
    }
}

// ===========================================================================
// Kernel 1: per-edge precompute + zero histogram + derive N/deg.
// ===========================================================================
template <int K>
__global__ void __launch_bounds__(256) smeam_edge_kernel_ct(
    const float* __restrict__ r, const float* __restrict__ fy,
    const int* __restrict__ dst, int E) {
    __shared__ float4 sf[K - 1];
    if (threadIdx.x == 0) build_spline_reg<K>(fy, CUTOFF / (float)(K - 1), sf);
    __syncthreads();

    int i = blockIdx.x * blockDim.x + threadIdx.x;
    if (i == 0) {
        int N = __ldg(&dst[E - 1]) + 1;
        g_N = N;
        g_degv = E / N;
    }
    if (i >= E) return;
    g_cnt[i] = 0;  // N <= E, covers the histogram range

    float x = r[3 * i + 0];
    float y = r[3 * i + 1];
    float z = r[3 * i + 2];
    float d2 = x * x + y * y + z * z;
    float invl = rsqrtf(d2);
    float l = d2 * invl;

    constexpr float hf = CUTOFF / (float)(K - 1);
    constexpr float inv_hf = (float)(K - 1) / CUTOFF;
    int idx = min(max((int)(l * inv_hf), 0), K - 2);
    float s = l - (float)idx * hf;
    float4 cf = sf[idx];
    float fv = cf.x + s * (cf.y + s * (cf.z + s * cf.w));

    g_edge[i] = make_float4(x * invl, y * invl, z * invl, fv);
}

// ===========================================================================
// Kernel 2: histogram of src + zero cursors.
// ===========================================================================
__global__ void __launch_bounds__(256) smeam_count_kernel(
    const int* __restrict__ src, int E) {
    int i = blockIdx.x * blockDim.x + threadIdx.x;
    if (i >= E) return;
    g_cur[i] = 0;
    atomicAdd(&g_cnt[src[i]], 1);
}

// ===========================================================================
// Kernel 3: exclusive scan of g_cnt[0..N) -> g_off (single block).
// ===========================================================================
__global__ void __launch_bounds__(1024) smeam_scan_kernel() {
    __shared__ int sh[1024];
    int N = g_N;
    int t = threadIdx.x;
    int L = (N + 1023) >> 10;
    int s0 = t * L;
    int s1 = min(s0 + L, N);

    int sum = 0;
    for (int i = s0; i < s1; i++) sum += g_cnt[i];
    sh[t] = sum;
    __syncthreads();
#pragma unroll
    for (int o = 1; o < 1024; o <<= 1) {
        int v = (t >= o) ? sh[t - o] : 0;
        __syncthreads();
        sh[t] += v;
        __syncthreads();
    }
    int run = (t == 0) ? 0 : sh[t - 1];
    for (int i = s0; i < s1; i++) {
        g_off[i] = run;
        run += g_cnt[i];
    }
}

// ===========================================================================
// Kernel 4: scatter e2 indices into per-node buckets.
// ===========================================================================
__global__ void __launch_bounds__(256) smeam_fill_kernel(
    const int* __restrict__ src, int E) {
    int i = blockIdx.x * blockDim.x + threadIdx.x;
    if (i >= E) return;
    int s = src[i];
    int p = atomicAdd(&g_cur[s], 1);
    g_list[g_off[s] + p] = i;
}

// ===========================================================================
// Kernel 5: one warp per node. Partner block (u1, f1, src1) lives in
// registers (lane j owns partner j). Stream the node's e2 list in batches
// of 4 (broadcast loads), interleaved butterfly reductions.
// ===========================================================================
template <int K>
__global__ void __launch_bounds__(256) smeam_main_kernel_node(
    const int* __restrict__ src, const int* __restrict__ dst,
    const float* __restrict__ gy, float* __restrict__ out, int E) {
    __shared__ float4 sg[K - 1];
    if (threadIdx.x == 0) build_spline_reg<K>(gy, 2.0f / (float)(K - 1), sg);
    __syncthreads();

    const int lane = threadIdx.x & 31;
    const int warp = (blockIdx.x * blockDim.x + threadIdx.x) >> 5;
    const int W = (gridDim.x * blockDim.x) >> 5;
    const int N = g_N;
    const int deg = g_degv;

    constexpr float hg = 2.0f / (float)(K - 1);
    constexpr float inv_hg = (float)(K - 1) * 0.5f;

    if (deg <= 32) {
        for (int n = warp; n < N; n += W) {
            const int base1 = n * deg;
            float4 P = make_float4(0.f, 0.f, 0.f, 0.f);
            int s1 = -1;
            if (lane < deg) {
                P = g_edge[base1 + lane];
                s1 = __ldg(&src[base1 + lane]);
            }
            const int start = g_off[n];
            const int cnt = g_cnt[n];

            int i = 0;
            for (; i + 4 <= cnt; i += 4) {
                int e2[4], d2v[4];
                float4 u2[4];
#pragma unroll
                for (int k = 0; k < 4; k++) {
                    e2[k] = g_list[start + i + k];
                    u2[k] = g_edge[e2[k]];
                    d2v[k] = __ldg(&dst[e2[k]]);
                }
                float acc[4];
#pragma unroll
                for (int k = 0; k < 4; k++) {
                    float c = -(P.x * u2[k].x + P.y * u2[k].y + P.z * u2[k].z);
                    c = fminf(fmaxf(c, -1.0f), 1.0f);
                    float xc = c + 1.0f;
                    int idx = min((int)(xc * inv_hg), K - 2);
                    float s = xc - (float)idx * hg;
                    float4 cf = sg[idx];
                    float gv = cf.x + s * (cf.y + s * (cf.z + s * cf.w));
                    acc[k] = (s1 != d2v[k]) ? P.w * gv : 0.0f;
                }
#pragma unroll
                for (int o = 16; o; o >>= 1) {
#pragma unroll
                    for (int k = 0; k < 4; k++)
                        acc[k] += __shfl_xor_sync(0xffffffffu, acc[k], o);
                }
                if (lane == 0) {
#pragma unroll
                    for (int k = 0; k < 4; k++)
                        out[e2[k]] = acc[k] * u2[k].w;
                }
            }
            for (; i < cnt; i++) {
                int e2 = g_list[start + i];
                float4 u2 = g_edge[e2];
                int d2v = __ldg(&dst[e2]);
                float c = -(P.x * u2.x + P.y * u2.y + P.z * u2.z);
                c = fminf(fmaxf(c, -1.0f), 1.0f);
                float xc = c + 1.0f;
                int idx = min((int)(xc * inv_hg), K - 2);
                float s = xc - (float)idx * hg;
                float4 cf = sg[idx];
                float gv = cf.x + s * (cf.y + s * (cf.z + s * cf.w));
                float acc = (s1 != d2v) ? P.w * gv : 0.0f;
#pragma unroll
                for (int o = 16; o; o >>= 1)
                    acc += __shfl_xor_sync(0xffffffffu, acc, o);
                if (lane == 0) out[e2] = acc * u2.w;
            }
        }
    } else {
        // deg > 32: partner block reloaded per e2 per strip (generic path).
        for (int n = warp; n < N; n += W) {
            const int base1 = n * deg;
            const int start = g_off[n];
            const int cnt = g_cnt[n];
            for (int i = 0; i < cnt; i++) {
                int e2 = g_list[start + i];
                float4 u2 = g_edge[e2];
                int d2v = __ldg(&dst[e2]);
                float acc = 0.0f;
                for (int j = lane; j < deg; j += 32) {
                    float4 P = g_edge[base1 + j];
                    int s1 = __ldg(&src[base1 + j]);
                    float c = -(P.x * u2.x + P.y * u2.y + P.z * u2.z);
                    c = fminf(fmaxf(c, -1.0f), 1.0f);
                    float xc = c + 1.0f;
                    int idx = min((int)(xc * inv_hg), K - 2);
                    float s = xc - (float)idx * hg;
                    float4 cf = sg[idx];
                    float gv = cf.x + s * (cf.y + s * (cf.z + s * cf.w));
                    acc += (s1 != d2v) ? P.w * gv : 0.0f;
                }
#pragma unroll
                for (int o = 16; o; o >>= 1)
                    acc += __shfl_xor_sync(0xffffffffu, acc, o);
                if (lane == 0) out[e2] = acc * u2.w;
            }
        }
    }
}

// ===========================================================================
// Generic-K fallback (runtime K) — round-1 style.
// ===========================================================================
__device__ void build_spline_rt(const float* y, int K, float h, float4* outc) {
    double dy[MAXK];
    for (int i = 0; i < K - 1; i++) dy[i] = ((double)y[i + 1] - (double)y[i]) / (double)h;
    int n = K - 2;
    double M[MAXK];
    for (int i = 0; i < K; i++) M[i] = 0.0;
    if (n > 0) {
        double cp[MAXK], dp[MAXK];
        double hh = (double)h;
        cp[0] = hh / (4.0 * hh);
        dp[0] = 6.0 * (dy[1] - dy[0]) / (4.0 * hh);
        for (int i = 1; i < n; i++) {
            double denom = 4.0 * hh - hh * cp[i - 1];
            cp[i] = hh / denom;
            dp[i] = (6.0 * (dy[i + 1] - dy[i]) - hh * dp[i - 1]) / denom;
        }
        double x = dp[n - 1];
        M[n] = x;
        for (int i = n - 2; i >= 0; i--) { x = dp[i] - cp[i] * x; M[i + 1] = x; }
    }
    for (int i = 0; i < K - 1; i++) {
        outc[i] = make_float4((float)y[i],
                              (float)(dy[i] - (double)h * (2.0 * M[i] + M[i + 1]) / 6.0),
                              (float)(M[i] / 2.0),
                              (float)((M[i + 1] - M[i]) / (6.0 * (double)h)));
    }
}

__global__ void smeam_build_kernel_rt(const float* fy, const float* gy,
                                      const int* dst, int E, int K) {
    int N = dst[E - 1] + 1;
    g_deg = E / N;
    build_spline_rt(fy, K, CUTOFF / (float)(K - 1), g_fc);
    build_spline_rt(gy, K, 2.0f / (float)(K - 1), g_gc);
}

__global__ void smeam_edge_kernel_rt(const float* __restrict__ r, int E, int K) {
    int i = blockIdx.x * blockDim.x + threadIdx.x;
    if (i >= E) return;
    float x = r[3 * i + 0], y = r[3 * i + 1], z = r[3 * i + 2];
    float d2 = x * x + y * y + z * z;
    float invl = rsqrtf(d2);
    float l = d2 * invl;
    float hf = CUTOFF / (float)(K - 1);
    float inv_hf = (float)(K - 1) / CUTOFF;
    int idx = min(max((int)floorf(l * inv_hf), 0), K - 2);
    float s = l - (float)idx * hf;
    float4 cf = g_fc[idx];
    g_edge[i] = make_float4(x * invl, y * invl, z * invl,
                            cf.x + s * (cf.y + s * (cf.z + s * cf.w)));
}

__global__ void smeam_main_kernel_rt(const int* __restrict__ src,
                                     const int* __restrict__ dst,
                                     float* __restrict__ out, int E, int K) {
    int warp = (blockIdx.x * blockDim.x + threadIdx.x) >> 5;
    int lane = threadIdx.x & 31;
    if (warp >= E) return;
    int e2 = warp;
    float4 u2 = g_edge[e2];
    int s2 = src[e2], d2 = dst[e2];
    int deg = g_deg;
    float hg = 2.0f / (float)(K - 1);
    float inv_hg = (float)(K - 1) * 0.5f;
    float acc = 0.0f;
    for (int j = lane; j < deg; j += 32) {
        int e1 = s2 * deg + j;
        float4 u1 = g_edge[e1];
        int s1 = src[e1];
        float c = -(u1.x * u2.x + u1.y * u2.y + u1.z * u2.z);
        c = fminf(fmaxf(c, -1.0f), 1.0f);
        float xc = c + 1.0f;
        int idx = min(max((int)floorf(xc * inv_hg), 0), K - 2);
        float s = xc - (float)idx * hg;
        float4 cf = g_gc[idx];
        float gv = cf.x + s * (cf.y + s * (cf.z + s * cf.w));
        acc += (s1 != d2) ? u1.w * u2.w * gv : 0.0f;
    }
#pragma unroll
    for (int o = 16; o; o >>= 1) acc += __shfl_down_sync(0xffffffffu, acc, o);
    if (lane == 0) out[e2] = acc;
}

// ===========================================================================
template <int K>
static void launch_ct(const float* r, const float* fy, const float* gy,
                      const int* src, const int* dst, float* out, int E) {
    int t = 256;
    int eb = (E + t - 1) / t;
    smeam_edge_kernel_ct<K><<<eb, t>>>(r, fy, dst, E);
    smeam_count_kernel<<<eb, t>>>(src, E);
    smeam_scan_kernel<<<1, 1024>>>();
    smeam_fill_kernel<<<eb, t>>>(src, E);
    // 148 SMs x 8 blocks of 256 -> 9472 warps, grid-stride over nodes.
    smeam_main_kernel_node<K><<<1184, 256>>>(src, dst, gy, out, E);
}

extern "C" void kernel_launch(void* const* d_in, const int* in_sizes, int n_in,
                              void* d_out, int out_size) {
    const float* r   = (const float*)d_in[0];
    const float* fy  = (const float*)d_in[1];
    const float* gy  = (const float*)d_in[2];
    const int*   src = (const int*)d_in[3];
    const int*   dst = (const int*)d_in[4];
    float*       out = (float*)d_out;

    int E = in_sizes[3];
    int K = in_sizes[1];

    switch (K) {
        case 3: launch_ct<3>(r, fy, gy, src, dst, out, E); break;
        case 4: launch_ct<4>(r, fy, gy, src, dst, out, E); break;
        case 5: launch_ct<5>(r, fy, gy, src, dst, out, E); break;
        case 6: launch_ct<6>(r, fy, gy, src, dst, out, E); break;
        case 7: launch_ct<7>(r, fy, gy, src, dst, out, E); break;
        case 8: launch_ct<8>(r, fy, gy, src, dst, out, E); break;
        case 9: launch_ct<9>(r, fy, gy, src, dst, out, E); break;
        default: {
            smeam_build_kernel_rt<<<1, 1>>>(fy, gy, dst, E, K);
            int t = 256;
            smeam_edge_kernel_rt<<<(E + t - 1) / t, t>>>(r, E, K);
            long total = (long)E * 32;
            unsigned blocks = (unsigned)((total + t - 1) / t);
            smeam_main_kernel_rt<<<blocks, t>>>(src, dst, out, E, K);
            break;
        }
    }
}

// round 4
// speedup vs baseline: 1.2180x; 1.2180x over previous
#include <cuda_runtime.h>

#define CUTOFF 8.0f
#define MAXK 32
#define MAXE (1 << 20)

// Per-edge precompute: (ux, uy, uz, f(|r|)) where u = r/|r|.
__device__ float4 g_edge[MAXE];
// Fixed-capacity per-node buckets (cap = 2*deg, total 2E <= 2*MAXE slots).
__device__ int g_cnt[MAXE];          // per-node incoming-e2 count (self-cleaned)
__device__ int g_list[2 * MAXE];     // bucket storage
__device__ int g_ovf[MAXE];          // overflow e2 list (rare)
__device__ int g_ovf_n;              // overflow count (self-cleaned)
__device__ int g_done;               // cleanup ticket
__device__ int g_N;
__device__ int g_degv;
// Fallback-path coefficient storage (generic K only).
__device__ float4 g_fc[MAXK];
__device__ float4 g_gc[MAXK];
__device__ int    g_deg;

// ===========================================================================
// Compile-time-K natural cubic spline (uniform knots). All-register Thomas.
// ===========================================================================
template <int K>
__device__ __forceinline__ void build_spline_reg(const float* __restrict__ y,
                                                 float h, float4* sh_out) {
    float yv[K];
#pragma unroll
    for (int i = 0; i < K; i++) yv[i] = y[i];

    const float inv_h = 1.0f / h;
    float dy[K - 1];
#pragma unroll
    for (int i = 0; i < K - 1; i++) dy[i] = (yv[i + 1] - yv[i]) * inv_h;

    constexpr int n = K - 2;
    float M[K];
    M[0] = 0.0f;
    M[K - 1] = 0.0f;
    if (n > 0) {
        float cp[n], dp[n];
        cp[0] = 0.25f;
        dp[0] = 6.0f * (dy[1] - dy[0]) * inv_h * 0.25f;
#pragma unroll
        for (int i = 1; i < n; i++) {
            float rd = 1.0f / (4.0f - cp[i - 1]);
            cp[i] = rd;
            dp[i] = (6.0f * (dy[i + 1] - dy[i]) * inv_h - dp[i - 1]) * rd;
        }
        M[n] = dp[n - 1];
#pragma unroll
        for (int i = n - 2; i >= 0; i--) M[i + 1] = dp[i] - cp[i] * M[i + 2];
    }

    constexpr float SIXTH = 1.0f / 6.0f;
#pragma unroll
    for (int i = 0; i < K - 1; i++) {
        sh_out[i] = make_float4(yv[i],
                                dy[i] - h * (2.0f * M[i] + M[i + 1]) * SIXTH,
                                0.5f * M[i],
                                (M[i + 1] - M[i]) * inv_h * SIXTH);
    }
}

// ===========================================================================
// Kernel 1 (fused): per-edge precompute (u, f(|r|)) + bucket fill.
// ===========================================================================
template <int K>
__global__ void __launch_bounds__(256) smeam_edge_fill_kernel(
    const float* __restrict__ r, const float* __restrict__ fy,
    const int* __restrict__ src, const int* __restrict__ dst, int E) {
    __shared__ float4 sf[K - 1];
    __shared__ int sh_cap;
    if (threadIdx.x == 0) {
        build_spline_reg<K>(fy, CUTOFF / (float)(K - 1), sf);
        int N = __ldg(&dst[E - 1]) + 1;
        int deg = E / N;
        sh_cap = 2 * deg;
        g_N = N;          // benign duplicate writes across blocks
        g_degv = deg;
    }
    __syncthreads();

    int i = blockIdx.x * blockDim.x + threadIdx.x;
    if (i >= E) return;

    float x = r[3 * i + 0];
    float y = r[3 * i + 1];
    float z = r[3 * i + 2];
    float d2 = x * x + y * y + z * z;
    float invl = rsqrtf(d2);
    float l = d2 * invl;

    constexpr float hf = CUTOFF / (float)(K - 1);
    constexpr float inv_hf = (float)(K - 1) / CUTOFF;
    int idx = min(max((int)(l * inv_hf), 0), K - 2);
    float s = l - (float)idx * hf;
    float4 cf = sf[idx];
    float fv = cf.x + s * (cf.y + s * (cf.z + s * cf.w));
    g_edge[i] = make_float4(x * invl, y * invl, z * invl, fv);

    // bucket fill: group e2 = i under node src[i]
    int sn = src[i];
    int cap = sh_cap;
    int p = atomicAdd(&g_cnt[sn], 1);
    if (p < cap) {
        g_list[sn * cap + p] = i;
    } else {
        int q = atomicAdd(&g_ovf_n, 1);
        g_ovf[q] = i;
    }
}

// ===========================================================================
// Kernel 2: one warp per node. Partner block (u1, f1, src1) in registers
// (lane j owns partner j). Stream the node's e2 bucket in batches of 4
// (all loads warp-broadcast), interleaved butterfly reductions.
// Zeroes g_cnt[n] after use (self-cleaning for graph replay).
// ===========================================================================
template <int K>
__global__ void __launch_bounds__(256) smeam_main_kernel_node(
    const int* __restrict__ src, const int* __restrict__ dst,
    const float* __restrict__ gy, float* __restrict__ out, int E) {
    __shared__ float4 sg[K - 1];
    if (threadIdx.x == 0) build_spline_reg<K>(gy, 2.0f / (float)(K - 1), sg);
    __syncthreads();

    const int lane = threadIdx.x & 31;
    const int warp = (blockIdx.x * blockDim.x + threadIdx.x) >> 5;
    const int W = (gridDim.x * blockDim.x) >> 5;
    const int N = g_N;
    const int deg = g_degv;
    const int cap = 2 * deg;

    constexpr float hg = 2.0f / (float)(K - 1);
    constexpr float inv_hg = (float)(K - 1) * 0.5f;

    if (deg <= 32) {
        for (int n = warp; n < N; n += W) {
            const int base1 = n * deg;
            float4 P = make_float4(0.f, 0.f, 0.f, 0.f);
            int s1 = -1;
            if (lane < deg) {
                P = g_edge[base1 + lane];
                s1 = __ldg(&src[base1 + lane]);
            }
            const int start = n * cap;
            int cnt = g_cnt[n];
            if (lane == 0) g_cnt[n] = 0;          // self-clean
            cnt = min(cnt, cap);

            int i = 0;
            for (; i + 4 <= cnt; i += 4) {
                int e2[4], d2v[4];
                float4 u2[4];
#pragma unroll
                for (int k = 0; k < 4; k++) {
                    e2[k] = g_list[start + i + k];
                    u2[k] = g_edge[e2[k]];
                    d2v[k] = __ldg(&dst[e2[k]]);
                }
                float acc[4];
#pragma unroll
                for (int k = 0; k < 4; k++) {
                    float c = -(P.x * u2[k].x + P.y * u2[k].y + P.z * u2[k].z);
                    c = fminf(fmaxf(c, -1.0f), 1.0f);
                    float xc = c + 1.0f;
                    int idx = min((int)(xc * inv_hg), K - 2);
                    float s = xc - (float)idx * hg;
                    float4 cf = sg[idx];
                    float gv = cf.x + s * (cf.y + s * (cf.z + s * cf.w));
                    acc[k] = (s1 != d2v[k]) ? P.w * gv : 0.0f;
                }
#pragma unroll
                for (int o = 16; o; o >>= 1) {
#pragma unroll
                    for (int k = 0; k < 4; k++)
                        acc[k] += __shfl_xor_sync(0xffffffffu, acc[k], o);
                }
                if (lane == 0) {
#pragma unroll
                    for (int k = 0; k < 4; k++)
                        out[e2[k]] = acc[k] * u2[k].w;
                }
            }
            for (; i < cnt; i++) {
                int e2 = g_list[start + i];
                float4 u2 = g_edge[e2];
                int d2v = __ldg(&dst[e2]);
                float c = -(P.x * u2.x + P.y * u2.y + P.z * u2.z);
                c = fminf(fmaxf(c, -1.0f), 1.0f);
                float xc = c + 1.0f;
                int idx = min((int)(xc * inv_hg), K - 2);
                float s = xc - (float)idx * hg;
                float4 cf = sg[idx];
                float gv = cf.x + s * (cf.y + s * (cf.z + s * cf.w));
                float acc = (s1 != d2v) ? P.w * gv : 0.0f;
#pragma unroll
                for (int o = 16; o; o >>= 1)
                    acc += __shfl_xor_sync(0xffffffffu, acc, o);
                if (lane == 0) out[e2] = acc * u2.w;
            }
        }
    } else {
        // deg > 32: strip-mined partner loop.
        for (int n = warp; n < N; n += W) {
            const int base1 = n * deg;
            const int start = n * cap;
            int cnt = g_cnt[n];
            if (lane == 0) g_cnt[n] = 0;
            cnt = min(cnt, cap);
            for (int i = 0; i < cnt; i++) {
                int e2 = g_list[start + i];
                float4 u2 = g_edge[e2];
                int d2v = __ldg(&dst[e2]);
                float acc = 0.0f;
                for (int j = lane; j < deg; j += 32) {
                    float4 P = g_edge[base1 + j];
                    int s1 = __ldg(&src[base1 + j]);
                    float c = -(P.x * u2.x + P.y * u2.y + P.z * u2.z);
                    c = fminf(fmaxf(c, -1.0f), 1.0f);
                    float xc = c + 1.0f;
                    int idx = min((int)(xc * inv_hg), K - 2);
                    float s = xc - (float)idx * hg;
                    float4 cf = sg[idx];
                    float gv = cf.x + s * (cf.y + s * (cf.z + s * cf.w));
                    acc += (s1 != d2v) ? P.w * gv : 0.0f;
                }
#pragma unroll
                for (int o = 16; o; o >>= 1)
                    acc += __shfl_xor_sync(0xffffffffu, acc, o);
                if (lane == 0) out[e2] = acc * u2.w;
            }
        }
    }
}

// ===========================================================================
// Kernel 3: overflow cleanup (warp per overflow e2; normally a no-op).
// Last block zeroes the overflow counter for the next replay.
// ===========================================================================
template <int K>
__global__ void __launch_bounds__(256) smeam_cleanup_kernel(
    const int* __restrict__ src, const int* __restrict__ dst,
    const float* __restrict__ gy, float* __restrict__ out, int E) {
    __shared__ float4 sg[K - 1];
    const int n_ovf = g_ovf_n;
    if (n_ovf > 0) {
        if (threadIdx.x == 0) build_spline_reg<K>(gy, 2.0f / (float)(K - 1), sg);
        __syncthreads();

        const int lane = threadIdx.x & 31;
        const int warp = (blockIdx.x * blockDim.x + threadIdx.x) >> 5;
        const int W = (gridDim.x * blockDim.x) >> 5;
        const int deg = g_degv;

        constexpr float hg = 2.0f / (float)(K - 1);
        constexpr float inv_hg = (float)(K - 1) * 0.5f;

        for (int v = warp; v < n_ovf; v += W) {
            int e2 = g_ovf[v];
            float4 u2 = g_edge[e2];
            int s2 = __ldg(&src[e2]);
            int d2v = __ldg(&dst[e2]);
            float acc = 0.0f;
            for (int j = lane; j < deg; j += 32) {
                float4 P = g_edge[s2 * deg + j];
                int s1 = __ldg(&src[s2 * deg + j]);
                float c = -(P.x * u2.x + P.y * u2.y + P.z * u2.z);
                c = fminf(fmaxf(c, -1.0f), 1.0f);
                float xc = c + 1.0f;
                int idx = min((int)(xc * inv_hg), K - 2);
                float s = xc - (float)idx * hg;
                float4 cf = sg[idx];
                float gv = cf.x + s * (cf.y + s * (cf.z + s * cf.w));
                acc += (s1 != d2v) ? P.w * gv : 0.0f;
            }
#pragma unroll
            for (int o = 16; o; o >>= 1)
                acc += __shfl_xor_sync(0xffffffffu, acc, o);
            if (lane == 0) out[e2] = acc * u2.w;
        }
        __syncthreads();
    }
    // ticket: last block resets overflow counter
    if (threadIdx.x == 0) {
        int d = atomicAdd(&g_done, 1);
        if (d == (int)gridDim.x - 1) {
            g_ovf_n = 0;
            g_done = 0;
        }
    }
}

// ===========================================================================
// Generic-K fallback (runtime K) — correctness-only path.
// ===========================================================================
__device__ void build_spline_rt(const float* y, int K, float h, float4* outc) {
    double dy[MAXK];
    for (int i = 0; i < K - 1; i++) dy[i] = ((double)y[i + 1] - (double)y[i]) / (double)h;
    int n = K - 2;
    double M[MAXK];
    for (int i = 0; i < K; i++) M[i] = 0.0;
    if (n > 0) {
        double cp[MAXK], dp[MAXK];
        double hh = (double)h;
        cp[0] = hh / (4.0 * hh);
        dp[0] = 6.0 * (dy[1] - dy[0]) / (4.0 * hh);
        for (int i = 1; i < n; i++) {
            double denom = 4.0 * hh - hh * cp[i - 1];
            cp[i] = hh / denom;
            dp[i] = (6.0 * (dy[i + 1] - dy[i]) - hh * dp[i - 1]) / denom;
        }
        double x = dp[n - 1];
        M[n] = x;
        for (int i = n - 2; i >= 0; i--) { x = dp[i] - cp[i] * x; M[i + 1] = x; }
    }
    for (int i = 0; i < K - 1; i++) {
        outc[i] = make_float4((float)y[i],
                              (float)(dy[i] - (double)h * (2.0 * M[i] + M[i + 1]) / 6.0),
                              (float)(M[i] / 2.0),
                              (float)((M[i + 1] - M[i]) / (6.0 * (double)h)));
    }
}

__global__ void smeam_build_kernel_rt(const float* fy, const float* gy,
                                      const int* dst, int E, int K) {
    int N = dst[E - 1] + 1;
    g_deg = E / N;
    build_spline_rt(fy, K, CUTOFF / (float)(K - 1), g_fc);
    build_spline_rt(gy, K, 2.0f / (float)(K - 1), g_gc);
}

__global__ void smeam_edge_kernel_rt(const float* __restrict__ r, int E, int K) {
    int i = blockIdx.x * blockDim.x + threadIdx.x;
    if (i >= E) return;
    float x = r[3 * i + 0], y = r[3 * i + 1], z = r[3 * i + 2];
    float d2 = x * x + y * y + z * z;
    float invl = rsqrtf(d2);
    float l = d2 * invl;
    float hf = CUTOFF / (float)(K - 1);
    float inv_hf = (float)(K - 1) / CUTOFF;
    int idx = min(max((int)floorf(l * inv_hf), 0), K - 2);
    float s = l - (float)idx * hf;
    float4 cf = g_fc[idx];
    g_edge[i] = make_float4(x * invl, y * invl, z * invl,
                            cf.x + s * (cf.y + s * (cf.z + s * cf.w)));
}

__global__ void smeam_main_kernel_rt(const int* __restrict__ src,
                                     const int* __restrict__ dst,
                                     float* __restrict__ out, int E, int K) {
    int warp = (blockIdx.x * blockDim.x + threadIdx.x) >> 5;
    int lane = threadIdx.x & 31;
    if (warp >= E) return;
    int e2 = warp;
    float4 u2 = g_edge[e2];
    int s2 = src[e2], d2 = dst[e2];
    int deg = g_deg;
    float hg = 2.0f / (float)(K - 1);
    float inv_hg = (float)(K - 1) * 0.5f;
    float acc = 0.0f;
    for (int j = lane; j < deg; j += 32) {
        int e1 = s2 * deg + j;
        float4 u1 = g_edge[e1];
        int s1 = src[e1];
        float c = -(u1.x * u2.x + u1.y * u2.y + u1.z * u2.z);
        c = fminf(fmaxf(c, -1.0f), 1.0f);
        float xc = c + 1.0f;
        int idx = min(max((int)floorf(xc * inv_hg), 0), K - 2);
        float s = xc - (float)idx * hg;
        float4 cf = g_gc[idx];
        float gv = cf.x + s * (cf.y + s * (cf.z + s * cf.w));
        acc += (s1 != d2) ? u1.w * u2.w * gv : 0.0f;
    }
#pragma unroll
    for (int o = 16; o; o >>= 1) acc += __shfl_down_sync(0xffffffffu, acc, o);
    if (lane == 0) out[e2] = acc;
}

// ===========================================================================
template <int K>
static void launch_ct(const float* r, const float* fy, const float* gy,
                      const int* src, const int* dst, float* out, int E) {
    int t = 256;
    int eb = (E + t - 1) / t;
    smeam_edge_fill_kernel<K><<<eb, t>>>(r, fy, src, dst, E);
    // 148 SMs x 8 blocks of 256 -> 9472 warps, grid-stride over nodes.
    smeam_main_kernel_node<K><<<1184, 256>>>(src, dst, gy, out, E);
    smeam_cleanup_kernel<K><<<64, 256>>>(src, dst, gy, out, E);
}

extern "C" void kernel_launch(void* const* d_in, const int* in_sizes, int n_in,
                              void* d_out, int out_size) {
    const float* r   = (const float*)d_in[0];
    const float* fy  = (const float*)d_in[1];
    const float* gy  = (const float*)d_in[2];
    const int*   src = (const int*)d_in[3];
    const int*   dst = (const int*)d_in[4];
    float*       out = (float*)d_out;

    int E = in_sizes[3];
    int K = in_sizes[1];

    switch (K) {
        case 3: launch_ct<3>(r, fy, gy, src, dst, out, E); break;
        case 4: launch_ct<4>(r, fy, gy, src, dst, out, E); break;
        case 5: launch_ct<5>(r, fy, gy, src, dst, out, E); break;
        case 6: launch_ct<6>(r, fy, gy, src, dst, out, E); break;
        case 7: launch_ct<7>(r, fy, gy, src, dst, out, E); break;
        case 8: launch_ct<8>(r, fy, gy, src, dst, out, E); break;
        case 9: launch_ct<9>(r, fy, gy, src, dst, out, E); break;
        default: {
            smeam_build_kernel_rt<<<1, 1>>>(fy, gy, dst, E, K);
            int t = 256;
            smeam_edge_kernel_rt<<<(E + t - 1) / t, t>>>(r, E, K);
            long total = (long)E * 32;
            unsigned blocks = (unsigned)((total + t - 1) / t);
            smeam_main_kernel_rt<<<blocks, t>>>(src, dst, out, E, K);
            break;
        }
    }
}

// round 5
// speedup vs baseline: 1.4148x; 1.1615x over previous
#include <cuda_runtime.h>

#define CUTOFF 8.0f
#define MAXK 32
#define MAXE (1 << 20)

// Per-edge precompute: (ux, uy, uz, f(|r|)) where u = r/|r|.
__device__ float4 g_edge[MAXE];
// Fixed-capacity per-node buckets (cap = 2*deg, total 2E <= 2*MAXE slots).
__device__ int g_cnt[MAXE];          // per-node incoming-e2 count (self-cleaned)
__device__ int g_list[2 * MAXE];     // bucket storage (e2 ids)
__device__ int g_ovf[MAXE];          // overflow e2 list (rare)
__device__ int g_ovf_n;              // overflow count (self-cleaned)
__device__ int g_done;               // cleanup ticket
__device__ int g_N;
__device__ int g_degv;
__device__ int g_shift;              // log2(deg) if pow2 else -1
// Fallback-path coefficient storage (generic K only).
__device__ float4 g_fc[MAXK];
__device__ float4 g_gc[MAXK];
__device__ int    g_deg;

// ===========================================================================
// Compile-time-K natural cubic spline (uniform knots). All-register Thomas.
// ===========================================================================
template <int K>
__device__ __forceinline__ void build_spline_reg(const float* __restrict__ y,
                                                 float h, float4* sh_out) {
    float yv[K];
#pragma unroll
    for (int i = 0; i < K; i++) yv[i] = y[i];

    const float inv_h = 1.0f / h;
    float dy[K - 1];
#pragma unroll
    for (int i = 0; i < K - 1; i++) dy[i] = (yv[i + 1] - yv[i]) * inv_h;

    constexpr int n = K - 2;
    float M[K];
    M[0] = 0.0f;
    M[K - 1] = 0.0f;
    if (n > 0) {
        float cp[n], dp[n];
        cp[0] = 0.25f;
        dp[0] = 6.0f * (dy[1] - dy[0]) * inv_h * 0.25f;
#pragma unroll
        for (int i = 1; i < n; i++) {
            float rd = 1.0f / (4.0f - cp[i - 1]);
            cp[i] = rd;
            dp[i] = (6.0f * (dy[i + 1] - dy[i]) * inv_h - dp[i - 1]) * rd;
        }
        M[n] = dp[n - 1];
#pragma unroll
        for (int i = n - 2; i >= 0; i--) M[i + 1] = dp[i] - cp[i] * M[i + 2];
    }

    constexpr float SIXTH = 1.0f / 6.0f;
#pragma unroll
    for (int i = 0; i < K - 1; i++) {
        sh_out[i] = make_float4(yv[i],
                                dy[i] - h * (2.0f * M[i] + M[i + 1]) * SIXTH,
                                0.5f * M[i],
                                (M[i + 1] - M[i]) * inv_h * SIXTH);
    }
}

// ===========================================================================
// Kernel 1 (fused): per-edge precompute (u, f(|r|)) + bucket fill.
// 2 independent edges per thread for MLP; atomic issued before float math.
// ===========================================================================
template <int K>
__global__ void __launch_bounds__(256) smeam_edge_fill_kernel(
    const float* __restrict__ r, const float* __restrict__ fy,
    const int* __restrict__ src, const int* __restrict__ dst, int E) {
    __shared__ float4 sf[K - 1];
    __shared__ int sh_cap;
    if (threadIdx.x == 0) {
        build_spline_reg<K>(fy, CUTOFF / (float)(K - 1), sf);
        int N = __ldg(&dst[E - 1]) + 1;
        int deg = E / N;
        sh_cap = 2 * deg;
        g_N = N;          // benign duplicate writes across blocks
        g_degv = deg;
        g_shift = ((deg & (deg - 1)) == 0) ? (__ffs(deg) - 1) : -1;
    }
    __syncthreads();

    const int T = gridDim.x * blockDim.x;
    const int gid = blockIdx.x * blockDim.x + threadIdx.x;
    const int cap = sh_cap;

    constexpr float hf = CUTOFF / (float)(K - 1);
    constexpr float inv_hf = (float)(K - 1) / CUTOFF;

    int ev[2];
    ev[0] = gid;
    ev[1] = gid + T;

#pragma unroll
    for (int q = 0; q < 2; q++) {
        int i = ev[q];
        if (i >= E) continue;

        // start the slow atomic chain early
        int sn = src[i];
        int p = atomicAdd(&g_cnt[sn], 1);

        float x = r[3 * i + 0];
        float y = r[3 * i + 1];
        float z = r[3 * i + 2];
        float d2 = x * x + y * y + z * z;
        float invl = rsqrtf(d2);
        float l = d2 * invl;

        int idx = min(max((int)(l * inv_hf), 0), K - 2);
        float s = fmaf((float)idx, -hf, l);
        float4 cf = sf[idx];
        float fv = fmaf(s, fmaf(s, fmaf(s, cf.w, cf.z), cf.y), cf.x);
        g_edge[i] = make_float4(x * invl, y * invl, z * invl, fv);

        if (p < cap) {
            g_list[sn * cap + p] = i;
        } else {
            int q2 = atomicAdd(&g_ovf_n, 1);
            g_ovf[q2] = i;
        }
    }
}

// ===========================================================================
// Kernel 2: one warp per node, half-warp split over e2 pairs.
// Lane l holds partners (l&15) and (l&15)+16 in registers (negated).
// The two 16-lane halves process two different e2 simultaneously.
// Zeroes g_cnt[n] after use (self-cleaning for graph replay).
// ===========================================================================
template <int K>
__global__ void __launch_bounds__(256) smeam_main_kernel_node(
    const int* __restrict__ src, const int* __restrict__ dst,
    const float* __restrict__ gy, float* __restrict__ out, int E) {
    __shared__ float4 sg[K - 1];
    if (threadIdx.x == 0) build_spline_reg<K>(gy, 2.0f / (float)(K - 1), sg);
    __syncthreads();

    const int lane = threadIdx.x & 31;
    const int hl = lane & 15;
    const int grp = lane >> 4;
    const int warp = (blockIdx.x * blockDim.x + threadIdx.x) >> 5;
    const int W = (gridDim.x * blockDim.x) >> 5;
    const int N = g_N;
    const int deg = g_degv;
    const int cap = 2 * deg;
    const int shift = g_shift;

    constexpr float hg = 2.0f / (float)(K - 1);
    constexpr float inv_hg = (float)(K - 1) * 0.5f;

    if (deg <= 32) {
        for (int n = warp; n < N; n += W) {
            const int base1 = n * deg;
            const int j0 = hl;
            const int j1 = hl + 16;
            float4 P0 = make_float4(0.f, 0.f, 0.f, 0.f);
            float4 P1 = make_float4(0.f, 0.f, 0.f, 0.f);
            int s10 = -0x7fffffff, s11 = -0x7fffffff;
            if (j0 < deg) {
                P0 = g_edge[base1 + j0];
                s10 = __ldg(&src[base1 + j0]);
            }
            if (j1 < deg) {
                P1 = g_edge[base1 + j1];
                s11 = __ldg(&src[base1 + j1]);
            }
            // negate so xc = 1 - dot(u1,u2) directly via FFMA chain
            P0.x = -P0.x; P0.y = -P0.y; P0.z = -P0.z;
            P1.x = -P1.x; P1.y = -P1.y; P1.z = -P1.z;

            const int start = n * cap;
            int cnt = g_cnt[n];
            if (lane == 0) g_cnt[n] = 0;  // self-clean
            cnt = min(cnt, cap);

            int i = 0;
            for (; i + 2 <= cnt; i += 2) {
                int2 ids = *reinterpret_cast<const int2*>(&g_list[start + i]);
                float4 r0 = g_edge[ids.x];
                float4 r1 = g_edge[ids.y];
                int e2 = grp ? ids.y : ids.x;
                float ux = grp ? r1.x : r0.x;
                float uy = grp ? r1.y : r0.y;
                float uz = grp ? r1.z : r0.z;
                float fw = grp ? r1.w : r0.w;
                int d2 = (shift >= 0) ? (e2 >> shift) : __ldg(&dst[e2]);

                // partner 0
                float xc = fmaf(P0.x, ux, fmaf(P0.y, uy, fmaf(P0.z, uz, 1.0f)));
                xc = fminf(fmaxf(xc, 0.0f), 2.0f);
                int idx = min((int)(xc * inv_hg), K - 2);
                float s = fmaf((float)idx, -hg, xc);
                float4 cf = sg[idx];
                float gv = fmaf(s, fmaf(s, fmaf(s, cf.w, cf.z), cf.y), cf.x);
                float acc = (s10 != d2) ? P0.w * gv : 0.0f;

                // partner 1
                float xc2 = fmaf(P1.x, ux, fmaf(P1.y, uy, fmaf(P1.z, uz, 1.0f)));
                xc2 = fminf(fmaxf(xc2, 0.0f), 2.0f);
                int idx2 = min((int)(xc2 * inv_hg), K - 2);
                float s2 = fmaf((float)idx2, -hg, xc2);
                float4 cf2 = sg[idx2];
                float gv2 = fmaf(s2, fmaf(s2, fmaf(s2, cf2.w, cf2.z), cf2.y), cf2.x);
                acc += (s11 != d2) ? P1.w * gv2 : 0.0f;

                // reduce within each 16-lane half
#pragma unroll
                for (int o = 8; o; o >>= 1)
                    acc += __shfl_xor_sync(0xffffffffu, acc, o);
                if (hl == 0) out[e2] = acc * fw;
            }
            if (i < cnt) {  // odd tail: single e2, group0 result is complete
                int e2 = g_list[start + i];
                float4 r0 = g_edge[e2];
                int d2 = (shift >= 0) ? (e2 >> shift) : __ldg(&dst[e2]);

                float xc = fmaf(P0.x, r0.x, fmaf(P0.y, r0.y, fmaf(P0.z, r0.z, 1.0f)));
                xc = fminf(fmaxf(xc, 0.0f), 2.0f);
                int idx = min((int)(xc * inv_hg), K - 2);
                float s = fmaf((float)idx, -hg, xc);
                float4 cf = sg[idx];
                float gv = fmaf(s, fmaf(s, fmaf(s, cf.w, cf.z), cf.y), cf.x);
                float acc = (s10 != d2) ? P0.w * gv : 0.0f;

                float xc2 = fmaf(P1.x, r0.x, fmaf(P1.y, r0.y, fmaf(P1.z, r0.z, 1.0f)));
                xc2 = fminf(fmaxf(xc2, 0.0f), 2.0f);
                int idx2 = min((int)(xc2 * inv_hg), K - 2);
                float s2 = fmaf((float)idx2, -hg, xc2);
                float4 cf2 = sg[idx2];
                float gv2 = fmaf(s2, fmaf(s2, fmaf(s2, cf2.w, cf2.z), cf2.y), cf2.x);
                acc += (s11 != d2) ? P1.w * gv2 : 0.0f;

#pragma unroll
                for (int o = 8; o; o >>= 1)
                    acc += __shfl_xor_sync(0xffffffffu, acc, o);
                if (lane == 0) out[e2] = acc * r0.w;
            }
        }
    } else {
        // deg > 32: strip-mined partner loop.
        for (int n = warp; n < N; n += W) {
            const int base1 = n * deg;
            const int start = n * cap;
            int cnt = g_cnt[n];
            if (lane == 0) g_cnt[n] = 0;
            cnt = min(cnt, cap);
            for (int i = 0; i < cnt; i++) {
                int e2 = g_list[start + i];
                float4 u2 = g_edge[e2];
                int d2v = (shift >= 0) ? (e2 >> shift) : __ldg(&dst[e2]);
                float acc = 0.0f;
                for (int j = lane; j < deg; j += 32) {
                    float4 P = g_edge[base1 + j];
                    int s1 = __ldg(&src[base1 + j]);
                    float xc = fmaf(-P.x, u2.x, fmaf(-P.y, u2.y, fmaf(-P.z, u2.z, 1.0f)));
                    xc = fminf(fmaxf(xc, 0.0f), 2.0f);
                    int idx = min((int)(xc * inv_hg), K - 2);
                    float s = fmaf((float)idx, -hg, xc);
                    float4 cf = sg[idx];
                    float gv = fmaf(s, fmaf(s, fmaf(s, cf.w, cf.z), cf.y), cf.x);
                    acc += (s1 != d2v) ? P.w * gv : 0.0f;
                }
#pragma unroll
                for (int o = 16; o; o >>= 1)
                    acc += __shfl_xor_sync(0xffffffffu, acc, o);
                if (lane == 0) out[e2] = acc * u2.w;
            }
        }
    }
}

// ===========================================================================
// Kernel 3: overflow cleanup (warp per overflow e2; normally a no-op).
// ===========================================================================
template <int K>
__global__ void __launch_bounds__(256) smeam_cleanup_kernel(
    const int* __restrict__ src, const int* __restrict__ dst,
    const float* __restrict__ gy, float* __restrict__ out, int E) {
    __shared__ float4 sg[K - 1];
    const int n_ovf = g_ovf_n;
    if (n_ovf > 0) {
        if (threadIdx.x == 0) build_spline_reg<K>(gy, 2.0f / (float)(K - 1), sg);
        __syncthreads();

        const int lane = threadIdx.x & 31;
        const int warp = (blockIdx.x * blockDim.x + threadIdx.x) >> 5;
        const int W = (gridDim.x * blockDim.x) >> 5;
        const int deg = g_degv;

        constexpr float hg = 2.0f / (float)(K - 1);
        constexpr float inv_hg = (float)(K - 1) * 0.5f;

        for (int v = warp; v < n_ovf; v += W) {
            int e2 = g_ovf[v];
            float4 u2 = g_edge[e2];
            int s2 = __ldg(&src[e2]);
            int d2v = __ldg(&dst[e2]);
            float acc = 0.0f;
            for (int j = lane; j < deg; j += 32) {
                float4 P = g_edge[s2 * deg + j];
                int s1 = __ldg(&src[s2 * deg + j]);
                float xc = fmaf(-P.x, u2.x, fmaf(-P.y, u2.y, fmaf(-P.z, u2.z, 1.0f)));
                xc = fminf(fmaxf(xc, 0.0f), 2.0f);
                int idx = min((int)(xc * inv_hg), K - 2);
                float s = fmaf((float)idx, -hg, xc);
                float4 cf = sg[idx];
                float gv = fmaf(s, fmaf(s, fmaf(s, cf.w, cf.z), cf.y), cf.x);
                acc += (s1 != d2v) ? P.w * gv : 0.0f;
            }
#pragma unroll
            for (int o = 16; o; o >>= 1)
                acc += __shfl_xor_sync(0xffffffffu, acc, o);
            if (lane == 0) out[e2] = acc * u2.w;
        }
        __syncthreads();
    }
    // ticket: last block resets overflow counter
    if (threadIdx.x == 0) {
        int d = atomicAdd(&g_done, 1);
        if (d == (int)gridDim.x - 1) {
            g_ovf_n = 0;
            g_done = 0;
        }
    }
}

// ===========================================================================
// Generic-K fallback (runtime K) — correctness-only path.
// ===========================================================================
__device__ void build_spline_rt(const float* y, int K, float h, float4* outc) {
    double dy[MAXK];
    for (int i = 0; i < K - 1; i++) dy[i] = ((double)y[i + 1] - (double)y[i]) / (double)h;
    int n = K - 2;
    double M[MAXK];
    for (int i = 0; i < K; i++) M[i] = 0.0;
    if (n > 0) {
        double cp[MAXK], dp[MAXK];
        double hh = (double)h;
        cp[0] = hh / (4.0 * hh);
        dp[0] = 6.0 * (dy[1] - dy[0]) / (4.0 * hh);
        for (int i = 1; i < n; i++) {
            double denom = 4.0 * hh - hh * cp[i - 1];
            cp[i] = hh / denom;
            dp[i] = (6.0 * (dy[i + 1] - dy[i]) - hh * dp[i - 1]) / denom;
        }
        double x = dp[n - 1];
        M[n] = x;
        for (int i = n - 2; i >= 0; i--) { x = dp[i] - cp[i] * x; M[i + 1] = x; }
    }
    for (int i = 0; i < K - 1; i++) {
        outc[i] = make_float4((float)y[i],
                              (float)(dy[i] - (double)h * (2.0 * M[i] + M[i + 1]) / 6.0),
                              (float)(M[i] / 2.0),
                              (float)((M[i + 1] - M[i]) / (6.0 * (double)h)));
    }
}

__global__ void smeam_build_kernel_rt(const float* fy, const float* gy,
                                      const int* dst, int E, int K) {
    int N = dst[E - 1] + 1;
    g_deg = E / N;
    build_spline_rt(fy, K, CUTOFF / (float)(K - 1), g_fc);
    build_spline_rt(gy, K, 2.0f / (float)(K - 1), g_gc);
}

__global__ void smeam_edge_kernel_rt(const float* __restrict__ r, int E, int K) {
    int i = blockIdx.x * blockDim.x + threadIdx.x;
    if (i >= E) return;
    float x = r[3 * i + 0], y = r[3 * i + 1], z = r[3 * i + 2];
    float d2 = x * x + y * y + z * z;
    float invl = rsqrtf(d2);
    float l = d2 * invl;
    float hf = CUTOFF / (float)(K - 1);
    float inv_hf = (float)(K - 1) / CUTOFF;
    int idx = min(max((int)floorf(l * inv_hf), 0), K - 2);
    float s = l - (float)idx * hf;
    float4 cf = g_fc[idx];
    g_edge[i] = make_float4(x * invl, y * invl, z * invl,
                            cf.x + s * (cf.y + s * (cf.z + s * cf.w)));
}

__global__ void smeam_main_kernel_rt(const int* __restrict__ src,
                                     const int* __restrict__ dst,
                                     float* __restrict__ out, int E, int K) {
    int warp = (blockIdx.x * blockDim.x + threadIdx.x) >> 5;
    int lane = threadIdx.x & 31;
    if (warp >= E) return;
    int e2 = warp;
    float4 u2 = g_edge[e2];
    int s2 = src[e2], d2 = dst[e2];
    int deg = g_deg;
    float hg = 2.0f / (float)(K - 1);
    float inv_hg = (float)(K - 1) * 0.5f;
    float acc = 0.0f;
    for (int j = lane; j < deg; j += 32) {
        int e1 = s2 * deg + j;
        float4 u1 = g_edge[e1];
        int s1 = src[e1];
        float c = -(u1.x * u2.x + u1.y * u2.y + u1.z * u2.z);
        c = fminf(fmaxf(c, -1.0f), 1.0f);
        float xc = c + 1.0f;
        int idx = min(max((int)floorf(xc * inv_hg), 0), K - 2);
        float s = xc - (float)idx * hg;
        float4 cf = g_gc[idx];
        float gv = cf.x + s * (cf.y + s * (cf.z + s * cf.w));
        acc += (s1 != d2) ? u1.w * u2.w * gv : 0.0f;
    }
#pragma unroll
    for (int o = 16; o; o >>= 1) acc += __shfl_down_sync(0xffffffffu, acc, o);
    if (lane == 0) out[e2] = acc;
}

// ===========================================================================
template <int K>
static void launch_ct(const float* r, const float* fy, const float* gy,
                      const int* src, const int* dst, float* out, int E) {
    int t = 256;
    int eb = (E + 2 * t - 1) / (2 * t);  // 2 edges per thread
    smeam_edge_fill_kernel<K><<<eb, t>>>(r, fy, src, dst, E);
    smeam_main_kernel_node<K><<<1250, 256>>>(src, dst, gy, out, E);
    smeam_cleanup_kernel<K><<<64, 256>>>(src, dst, gy, out, E);
}

extern "C" void kernel_launch(void* const* d_in, const int* in_sizes, int n_in,
                              void* d_out, int out_size) {
    const float* r   = (const float*)d_in[0];
    const float* fy  = (const float*)d_in[1];
    const float* gy  = (const float*)d_in[2];
    const int*   src = (const int*)d_in[3];
    const int*   dst = (const int*)d_in[4];
    float*       out = (float*)d_out;

    int E = in_sizes[3];
    int K = in_sizes[1];

    switch (K) {
        case 3: launch_ct<3>(r, fy, gy, src, dst, out, E); break;
        case 4: launch_ct<4>(r, fy, gy, src, dst, out, E); break;
        case 5: launch_ct<5>(r, fy, gy, src, dst, out, E); break;
        case 6: launch_ct<6>(r, fy, gy, src, dst, out, E); break;
        case 7: launch_ct<7>(r, fy, gy, src, dst, out, E); break;
        case 8: launch_ct<8>(r, fy, gy, src, dst, out, E); break;
        case 9: launch_ct<9>(r, fy, gy, src, dst, out, E); break;
        default: {
            smeam_build_kernel_rt<<<1, 1>>>(fy, gy, dst, E, K);
            int t = 256;
            smeam_edge_kernel_rt<<<(E + t - 1) / t, t>>>(r, E, K);
            long total = (long)E * 32;
            unsigned blocks = (unsigned)((total + t - 1) / t);
            smeam_main_kernel_rt<<<blocks, t>>>(src, dst, out, E, K);
            break;
        }
    }
}